// round 16
// baseline (speedup 1.0000x reference)
#include <cuda_runtime.h>
#include <math.h>

// ---------------------------------------------------------------------------
// AttentionLSTM forward, B=32 T=128 P=196 ENC=2048 DEC=ATT=EMB=512 V=10000.
// fp32 with packed fma.rn.f32x2.
// Prologue: k_mean, k_att1, k_init (proven).
// Recurrence: ONE persistent kernel (148 blocks x 256 thr) with a software
// grid barrier; stages communicate through L2 (cp.async.cg / __ldcg).
// All stage bodies are __noinline__ to keep the compiled kernel small.
// ---------------------------------------------------------------------------

#define B_   32
#define T_   128
#define P_   196
#define ENC_ 2048
#define DEC_ 512
#define ATT_ 512
#define EMB_ 512
#define V_   10000
#define XK_  3072
#define NCH_ 8
#define KCH_ (XK_ / NCH_)     // 384
#define BK_  32
#define NB_  148              // persistent grid (<= SM count, co-resident)

typedef unsigned long long u64;

__device__ __forceinline__ void fma2(u64& c, u64 a, u64 b) {
    asm("fma.rn.f32x2 %0, %1, %2, %0;" : "+l"(c) : "l"(a), "l"(b));
}
__device__ __forceinline__ float fold2(u64 v) {
    return __uint_as_float((unsigned)v) + __uint_as_float((unsigned)(v >> 32));
}
__device__ __forceinline__ float sigf(float x) { return 1.0f / (1.0f + expf(-x)); }

__device__ __forceinline__ unsigned sm32(const void* p) {
    return (unsigned)__cvta_generic_to_shared(p);
}
__device__ __forceinline__ void cpa16(unsigned dst, const float* src) {
    asm volatile("cp.async.cg.shared.global [%0], [%1], 16;" :: "r"(dst), "l"(src));
}
#define CP_COMMIT() asm volatile("cp.async.commit_group;")
#define CP_WAIT1()  asm volatile("cp.async.wait_group 1;")
#define CP_WAIT0()  asm volatile("cp.async.wait_group 0;")

// ----------------------------- device scratch ------------------------------
__device__ float g_att1[B_ * P_ * ATT_];         // written in prologue
__device__ float g_mean[B_ * ENC_];
__device__ float g_hbuf[2][B_ * DEC_];
__device__ float g_cbuf[2][B_ * DEC_];
__device__ float g_hnew[B_ * DEC_];
__device__ float g_att2[B_ * ATT_];
__device__ float g_gate[B_ * ENC_];
__device__ float g_xawe[B_ * ENC_];
__device__ float g_alpha[B_ * P_];
__device__ float g_cpart[NCH_ * B_ * 2048];
__device__ float g_ppart[4 * B_ * 2560];

// grid barrier state (persists across graph replays; relative-gen compare)
__device__ unsigned g_bar_cnt = 0;
__device__ unsigned g_bar_gen = 0;

__device__ __forceinline__ void gridbar() {
    __syncthreads();
    if (threadIdx.x == 0) {
        __threadfence();
        unsigned gen = *(volatile unsigned*)&g_bar_gen;   // read BEFORE add
        if (atomicAdd(&g_bar_cnt, 1u) == NB_ - 1u) {
            g_bar_cnt = 0;
            __threadfence();
            *(volatile unsigned*)&g_bar_gen = gen + 1u;
        } else {
            while (*(volatile unsigned*)&g_bar_gen == gen) __nanosleep(64);
        }
    }
    __syncthreads();
}

// ----------------------------- smem layouts --------------------------------
struct Tiles {                 // prologue 32x64 engine (proven)
    float xs[32][36];
    float ws[64][36];
};
struct Tiles2 {                // 32x128 engine (loop GEMMs)
    float xs[32][36];
    float ws[128][36];
};
struct EscSmem {
    float att2_s[ATT_];
    float w_s[ATT_];
    float e_s[224];
    float red[256];
};
union PSmem {
    Tiles2 tb[2];              // 46080 B
    EscSmem esc;
    float al[256];
};

__device__ __forceinline__ void mma_tile(const Tiles& s, u64 (&acc)[8][2], int tid) {
    int lane = tid & 31;
    int rb = (tid >> 5) * 8;
#pragma unroll
    for (int kq = 0; kq < 8; kq++) {
        ulonglong2 b0 = *(const ulonglong2*)&s.ws[lane][4 * kq];
        ulonglong2 b1 = *(const ulonglong2*)&s.ws[lane + 32][4 * kq];
#pragma unroll
        for (int i = 0; i < 8; i++) {
            ulonglong2 a = *(const ulonglong2*)&s.xs[rb + i][4 * kq];
            fma2(acc[i][0], a.x, b0.x);
            fma2(acc[i][0], a.y, b0.y);
            fma2(acc[i][1], a.x, b1.x);
            fma2(acc[i][1], a.y, b1.y);
        }
    }
}

__device__ __forceinline__ void mma_tile2(const Tiles2& s, u64 (&acc)[8][2],
                                          int lane, int rb, int cb2) {
#pragma unroll
    for (int kq = 0; kq < 8; kq++) {
        ulonglong2 b0 = *(const ulonglong2*)&s.ws[cb2 + lane][4 * kq];
        ulonglong2 b1 = *(const ulonglong2*)&s.ws[cb2 + lane + 32][4 * kq];
#pragma unroll
        for (int i = 0; i < 8; i++) {
            ulonglong2 a = *(const ulonglong2*)&s.xs[rb + i][4 * kq];
            fma2(acc[i][0], a.x, b0.x);
            fma2(acc[i][0], a.y, b0.y);
            fma2(acc[i][1], a.x, b1.x);
            fma2(acc[i][1], a.y, b1.y);
        }
    }
}

// ----------------------------- prologue kernels ----------------------------
__global__ __launch_bounds__(256) void k_mean(const float* __restrict__ bimgs) {
    int idx = blockIdx.x * 256 + threadIdx.x;
    int b = idx >> 11, e = idx & 2047;
    const float* p = bimgs + (size_t)b * P_ * ENC_ + e;
    float s = 0.f;
#pragma unroll 4
    for (int pp = 0; pp < P_; ++pp) s += p[(size_t)pp * ENC_];
    g_mean[b * ENC_ + e] = s * (1.0f / 196.0f);
}

__global__ __launch_bounds__(128, 4) void k_att1(
    const float* __restrict__ bimgs, const float* __restrict__ W0,
    const float* __restrict__ bias0)
{
    __shared__ __align__(16) Tiles tb[2];
    int tid = threadIdx.x, lane = tid & 31;
    int j0 = blockIdx.x * 64, r0 = blockIdx.y * 32;
    u64 acc[8][2];
#pragma unroll
    for (int i = 0; i < 8; i++) { acc[i][0] = 0ull; acc[i][1] = 0ull; }

    auto load = [&](int s, int k0) {
#pragma unroll
        for (int i2 = 0; i2 < 2; i2++) {
            int ff = i2 * 128 + tid, m = ff >> 3, q = ff & 7;
            cpa16(sm32(&tb[s].xs[m][q * 4]),
                  bimgs + (size_t)(r0 + m) * ENC_ + k0 + q * 4);
        }
#pragma unroll
        for (int i2 = 0; i2 < 4; i2++) {
            int ff = i2 * 128 + tid, c = ff >> 3, q = ff & 7;
            cpa16(sm32(&tb[s].ws[c][q * 4]),
                  W0 + (size_t)(j0 + c) * ENC_ + k0 + q * 4);
        }
        CP_COMMIT();
    };

    const int NIT = ENC_ / BK_;
    load(0, 0);
    for (int it = 0; it < NIT; ++it) {
        if (it + 1 < NIT) { load((it + 1) & 1, (it + 1) * BK_); CP_WAIT1(); }
        else              { CP_WAIT0(); }
        __syncthreads();
        mma_tile(tb[it & 1], acc, tid);
        __syncthreads();
    }
    int rb = (tid >> 5) * 8;
#pragma unroll
    for (int i = 0; i < 8; i++)
#pragma unroll
        for (int jj = 0; jj < 2; jj++) {
            int jg = j0 + lane + 32 * jj;
            g_att1[(size_t)(r0 + rb + i) * ATT_ + jg] = fold2(acc[i][jj]) + bias0[jg];
        }
}

__global__ __launch_bounds__(128, 4) void k_init(
    const float* __restrict__ Wh, const float* __restrict__ Wc,
    const float* __restrict__ bh, const float* __restrict__ bc)
{
    __shared__ __align__(16) Tiles tb[2];
    int tid = threadIdx.x, lane = tid & 31;
    int j0 = blockIdx.x * 64;
    u64 acc[8][2];
#pragma unroll
    for (int i = 0; i < 8; i++) { acc[i][0] = 0ull; acc[i][1] = 0ull; }

    auto load = [&](int s, int k0) {
#pragma unroll
        for (int i2 = 0; i2 < 2; i2++) {
            int ff = i2 * 128 + tid, m = ff >> 3, q = ff & 7;
            cpa16(sm32(&tb[s].xs[m][q * 4]), g_mean + (size_t)m * ENC_ + k0 + q * 4);
        }
#pragma unroll
        for (int i2 = 0; i2 < 4; i2++) {
            int ff = i2 * 128 + tid, c = ff >> 3, q = ff & 7;
            int jg = j0 + c;
            const float* src = (jg < DEC_) ? Wh + (size_t)jg * ENC_ + k0 + q * 4
                                           : Wc + (size_t)(jg - DEC_) * ENC_ + k0 + q * 4;
            cpa16(sm32(&tb[s].ws[c][q * 4]), src);
        }
        CP_COMMIT();
    };

    const int NIT = ENC_ / BK_;
    load(0, 0);
    for (int it = 0; it < NIT; ++it) {
        if (it + 1 < NIT) { load((it + 1) & 1, (it + 1) * BK_); CP_WAIT1(); }
        else              { CP_WAIT0(); }
        __syncthreads();
        mma_tile(tb[it & 1], acc, tid);
        __syncthreads();
    }
    int rb = (tid >> 5) * 8;
#pragma unroll
    for (int i = 0; i < 8; i++)
#pragma unroll
        for (int jj = 0; jj < 2; jj++) {
            int jg = j0 + lane + 32 * jj;
            int row = rb + i;
            float v = fold2(acc[i][jj]);
            if (jg < DEC_) g_hbuf[0][row * DEC_ + jg] = v + bh[jg];
            else           g_cbuf[0][row * DEC_ + (jg - DEC_)] = v + bc[jg - DEC_];
        }
}

// ----------------------------- persistent stages (noinline) ----------------
__device__ __noinline__ void escore_stage(
    int b, int t, EscSmem* Sp,
    const float* __restrict__ full_att_W, const float* __restrict__ full_att_b,
    const int* __restrict__ bxlen, float* __restrict__ out_alpha, int tid)
{
    EscSmem& S = *Sp;
    for (int i = tid; i < ATT_; i += 256) {
        S.att2_s[i] = __ldcg(&g_att2[b * ATT_ + i]);
        S.w_s[i] = full_att_W[i];
    }
    __syncthreads();
    int warp = tid >> 5, lane = tid & 31;
    float fb = full_att_b[0];
    for (int p = warp; p < P_; p += 8) {
        const float4* row = (const float4*)(g_att1 + ((size_t)b * P_ + p) * ATT_);
        float s = 0.f;
#pragma unroll
        for (int it = 0; it < 4; it++) {
            int k4 = lane + it * 32;
            float4 xv = row[k4];
            float4 av = *(const float4*)&S.att2_s[k4 * 4];
            float4 wv = *(const float4*)&S.w_s[k4 * 4];
            s = fmaf(fmaxf(xv.x + av.x, 0.f), wv.x, s);
            s = fmaf(fmaxf(xv.y + av.y, 0.f), wv.y, s);
            s = fmaf(fmaxf(xv.z + av.z, 0.f), wv.z, s);
            s = fmaf(fmaxf(xv.w + av.w, 0.f), wv.w, s);
        }
#pragma unroll
        for (int o = 16; o; o >>= 1) s += __shfl_xor_sync(0xffffffffu, s, o);
        if (!lane) S.e_s[p] = s + fb;
    }
    __syncthreads();
    float v = (tid < P_) ? S.e_s[tid] : -1e30f;
    S.red[tid] = v; __syncthreads();
    for (int o = 128; o; o >>= 1) { if (tid < o) S.red[tid] = fmaxf(S.red[tid], S.red[tid + o]); __syncthreads(); }
    float mx = S.red[0]; __syncthreads();
    float ex = (tid < P_) ? expf(v - mx) : 0.f;
    S.red[tid] = ex; __syncthreads();
    for (int o = 128; o; o >>= 1) { if (tid < o) S.red[tid] += S.red[tid + o]; __syncthreads(); }
    float inv = 1.0f / S.red[0];
    if (tid < P_) {
        float alpha = ex * inv;
        g_alpha[b * P_ + tid] = alpha;
        bool act = (t < bxlen[b]);
        out_alpha[((size_t)b * T_ + t) * P_ + tid] = act ? alpha : 0.f;
    }
}

__device__ __noinline__ void preds_tile(
    int task, int tt, Tiles2* tb,
    const float* __restrict__ fc_W, const float* __restrict__ fc_b,
    const int* __restrict__ bxlen, float* __restrict__ out_pred, int tid)
{
    int lane = tid & 31, w = tid >> 5;
    int rb = (w & 3) * 8, cb2 = (w >> 2) * 64;
    int j0 = task * 128;
    u64 acc[8][2];
#pragma unroll
    for (int i = 0; i < 8; i++) { acc[i][0] = 0ull; acc[i][1] = 0ull; }

    auto load = [&](int s, int k0) {
        { int m = tid >> 3, q = tid & 7;
          cpa16(sm32(&tb[s].xs[m][q * 4]), g_hnew + m * DEC_ + k0 + q * 4); }
#pragma unroll
        for (int i2 = 0; i2 < 4; i2++) {
            int ff = i2 * 256 + tid, c = ff >> 3, q = ff & 7;
            int jg = j0 + c; if (jg >= V_) jg = V_ - 1;
            cpa16(sm32(&tb[s].ws[c][q * 4]), fc_W + (size_t)jg * DEC_ + k0 + q * 4);
        }
        CP_COMMIT();
    };

    const int NIT = DEC_ / BK_;   // 16
    load(0, 0);
    for (int it = 0; it < NIT; ++it) {
        if (it + 1 < NIT) { load((it + 1) & 1, (it + 1) * BK_); CP_WAIT1(); }
        else              { CP_WAIT0(); }
        __syncthreads();
        mma_tile2(tb[it & 1], acc, lane, rb, cb2);
        __syncthreads();
    }
#pragma unroll
    for (int i = 0; i < 8; i++) {
        int row = rb + i;
#pragma unroll
        for (int jj = 0; jj < 2; jj++) {
            int jg = j0 + cb2 + lane + 32 * jj;
            if (jg < V_) {
                bool act = (tt < bxlen[row]);
                out_pred[((size_t)row * T_ + tt) * V_ + jg] =
                    act ? (fold2(acc[i][jj]) + fc_b[jg]) : 0.f;
            }
        }
    }
}

__device__ __noinline__ void awe_task(
    int b, int eb, const float* __restrict__ bimgs, float* al, int tid)
{
    __syncthreads();
    if (tid < P_) al[tid] = __ldcg(&g_alpha[b * P_ + tid]);
    __syncthreads();
    int e = eb * 256 + tid;
    const float* base = bimgs + (size_t)b * P_ * ENC_ + e;
    float s0 = 0.f, s1 = 0.f, s2 = 0.f, s3 = 0.f;
#pragma unroll 4
    for (int p = 0; p < P_; p += 4) {
        s0 = fmaf(al[p    ], base[(size_t)(p    ) * ENC_], s0);
        s1 = fmaf(al[p + 1], base[(size_t)(p + 1) * ENC_], s1);
        s2 = fmaf(al[p + 2], base[(size_t)(p + 2) * ENC_], s2);
        s3 = fmaf(al[p + 3], base[(size_t)(p + 3) * ENC_], s3);
    }
    g_xawe[b * ENC_ + e] = __ldcg(&g_gate[b * ENC_ + e]) * ((s0 + s1) + (s2 + s3));
}

__device__ __noinline__ void cell_tile(
    int col, int kc, int t, int par, Tiles2* tb, int* idx_s,
    const float* __restrict__ W_ih, const float* __restrict__ W_hh,
    const float* __restrict__ embW, const int* __restrict__ bx, int tid)
{
    int lane = tid & 31, w = tid >> 5;
    int rb = (w & 3) * 8, cb2 = (w >> 2) * 64;
    int j0 = col * 128;
    int kbeg = kc * KCH_;
    if (tid < 32) idx_s[tid] = bx[tid * T_ + t];
    __syncthreads();
    u64 acc[8][2];
#pragma unroll
    for (int i = 0; i < 8; i++) { acc[i][0] = 0ull; acc[i][1] = 0ull; }

    auto load = [&](int s, int k0) {
        { int m = tid >> 3, q = tid & 7;
          int kk = k0 + q * 4;
          const float* src;
          if (k0 < EMB_)             src = embW + (size_t)idx_s[m] * EMB_ + kk;
          else if (k0 < EMB_ + ENC_) src = g_xawe + m * ENC_ + (kk - EMB_);
          else                       src = g_hbuf[par] + m * DEC_ + (kk - (EMB_ + ENC_));
          cpa16(sm32(&tb[s].xs[m][q * 4]), src); }
#pragma unroll
        for (int i2 = 0; i2 < 4; i2++) {
            int ff = i2 * 256 + tid, c = ff >> 3, q = ff & 7;
            int kk = k0 + q * 4;
            int jg = j0 + c;
            const float* src = (k0 < EMB_ + ENC_)
                ? W_ih + (size_t)jg * (EMB_ + ENC_) + kk
                : W_hh + (size_t)jg * DEC_ + (kk - (EMB_ + ENC_));
            cpa16(sm32(&tb[s].ws[c][q * 4]), src);
        }
        CP_COMMIT();
    };

    const int NIT = KCH_ / BK_;   // 12
    load(0, kbeg);
    for (int it = 0; it < NIT; ++it) {
        if (it + 1 < NIT) { load((it + 1) & 1, kbeg + (it + 1) * BK_); CP_WAIT1(); }
        else              { CP_WAIT0(); }
        __syncthreads();
        mma_tile2(tb[it & 1], acc, lane, rb, cb2);
        __syncthreads();
    }
    float* dst = g_cpart + (size_t)kc * B_ * 2048;
#pragma unroll
    for (int i = 0; i < 8; i++)
#pragma unroll
        for (int jj = 0; jj < 2; jj++)
            dst[(size_t)(rb + i) * 2048 + j0 + cb2 + lane + 32 * jj] = fold2(acc[i][jj]);
}

__device__ __noinline__ void lstm_stage(
    const float* __restrict__ b_ih, const float* __restrict__ b_hh,
    const int* __restrict__ bxlen, int t, int par, int gid)
{
    if (gid >= B_ * DEC_) return;
    int m = gid >> 9, j = gid & 511;
    float s0 = b_ih[j] + b_hh[j];
    float s1 = b_ih[512 + j] + b_hh[512 + j];
    float s2 = b_ih[1024 + j] + b_hh[1024 + j];
    float s3 = b_ih[1536 + j] + b_hh[1536 + j];
#pragma unroll
    for (int kc = 0; kc < NCH_; kc++) {
        const float* p = g_cpart + ((size_t)kc * B_ + m) * 2048;
        s0 += __ldcg(&p[j]);
        s1 += __ldcg(&p[512 + j]);
        s2 += __ldcg(&p[1024 + j]);
        s3 += __ldcg(&p[1536 + j]);
    }
    float i_ = sigf(s0), f_ = sigf(s1), g_ = tanhf(s2), o_ = sigf(s3);
    float h_old = __ldcg(&g_hbuf[par][m * DEC_ + j]);
    float c_old = __ldcg(&g_cbuf[par][m * DEC_ + j]);
    float cn = f_ * c_old + i_ * g_;
    float hn = o_ * tanhf(cn);
    g_hnew[m * DEC_ + j] = hn;
    bool act = (t < bxlen[m]);
    g_hbuf[par ^ 1][m * DEC_ + j] = act ? hn : h_old;
    g_cbuf[par ^ 1][m * DEC_ + j] = act ? cn : c_old;
}

// att2+gate GEMM, K split 4x128.  task = colt*4 + kc;  colt in [0,20).
__device__ __noinline__ void a2g_tile(
    int task, const float* __restrict__ h2, Tiles2* tb,
    const float* __restrict__ dec_att_W, const float* __restrict__ f_beta_W,
    int tid)
{
    int lane = tid & 31, w = tid >> 5;
    int rb = (w & 3) * 8, cb2 = (w >> 2) * 64;
    int kc = task & 3, colt = task >> 2;
    int j0 = colt * 128;
    int kbeg = kc * 128;
    u64 acc[8][2];
#pragma unroll
    for (int i = 0; i < 8; i++) { acc[i][0] = 0ull; acc[i][1] = 0ull; }

    auto load = [&](int s, int k0) {
        { int m = tid >> 3, q = tid & 7;
          cpa16(sm32(&tb[s].xs[m][q * 4]), h2 + m * DEC_ + k0 + q * 4); }
#pragma unroll
        for (int i2 = 0; i2 < 4; i2++) {
            int ff = i2 * 256 + tid, c = ff >> 3, q = ff & 7;
            int jg = j0 + c;
            const float* src = (jg < ATT_)
                ? dec_att_W + (size_t)jg * DEC_ + k0 + q * 4
                : f_beta_W + (size_t)(jg - ATT_) * DEC_ + k0 + q * 4;
            cpa16(sm32(&tb[s].ws[c][q * 4]), src);
        }
        CP_COMMIT();
    };

    const int NIT = 4;            // 128 / BK_
    load(0, kbeg);
    for (int it = 0; it < NIT; ++it) {
        if (it + 1 < NIT) { load((it + 1) & 1, kbeg + (it + 1) * BK_); CP_WAIT1(); }
        else              { CP_WAIT0(); }
        __syncthreads();
        mma_tile2(tb[it & 1], acc, lane, rb, cb2);
        __syncthreads();
    }
#pragma unroll
    for (int i = 0; i < 8; i++) {
        int row = rb + i;
#pragma unroll
        for (int jj = 0; jj < 2; jj++) {
            int jg = j0 + cb2 + lane + 32 * jj;
            g_ppart[(size_t)(kc * B_ + row) * 2560 + jg] = fold2(acc[i][jj]);
        }
    }
}

__device__ __noinline__ void a2g_reduce(
    const float* __restrict__ dec_att_b, const float* __restrict__ f_beta_b,
    int gid)
{
    for (int i = gid; i < B_ * 2560; i += NB_ * 256) {
        int row = i / 2560, j = i - row * 2560;
        float s = __ldcg(&g_ppart[(size_t)(0 * B_ + row) * 2560 + j])
                + __ldcg(&g_ppart[(size_t)(1 * B_ + row) * 2560 + j])
                + __ldcg(&g_ppart[(size_t)(2 * B_ + row) * 2560 + j])
                + __ldcg(&g_ppart[(size_t)(3 * B_ + row) * 2560 + j]);
        if (j < ATT_) g_att2[row * ATT_ + j] = s + dec_att_b[j];
        else          g_gate[row * ENC_ + (j - ATT_)] = sigf(s + f_beta_b[j - ATT_]);
    }
}

// ----------------------------- persistent kernel ---------------------------
__global__ __launch_bounds__(256, 1) void k_loop(
    const float* __restrict__ bimgs, const int* __restrict__ bx,
    const int* __restrict__ bxlen, const float* __restrict__ embW,
    const float* __restrict__ dec_att_W, const float* __restrict__ dec_att_b,
    const float* __restrict__ full_att_W, const float* __restrict__ full_att_b,
    const float* __restrict__ f_beta_W, const float* __restrict__ f_beta_b,
    const float* __restrict__ W_ih, const float* __restrict__ b_ih,
    const float* __restrict__ W_hh, const float* __restrict__ b_hh,
    const float* __restrict__ fc_W, const float* __restrict__ fc_b,
    float* __restrict__ out_pred, float* __restrict__ out_alpha)
{
    __shared__ __align__(16) PSmem sm;
    __shared__ int idx_s[32];
    int bid = blockIdx.x, tid = threadIdx.x;
    int gid = bid * 256 + tid;

    // pre-loop: att2 + gate from h0 (hbuf[0])
    if (bid < 80) a2g_tile(bid, g_hbuf[0], sm.tb, dec_att_W, f_beta_W, tid);
    gridbar();
    a2g_reduce(dec_att_b, f_beta_b, gid);
    gridbar();

    for (int t = 0; t < T_; ++t) {
        int par = t & 1;

        // A: escore(t) blocks 0..31  ||  preds(t-1) blocks 32..110
        if (bid < 32)
            escore_stage(bid, t, &sm.esc, full_att_W, full_att_b, bxlen, out_alpha, tid);
        else if (t > 0 && bid - 32 < 79)
            preds_tile(bid - 32, t - 1, sm.tb, fc_W, fc_b, bxlen, out_pred, tid);
        gridbar();

        // B: awe(t) — 256 tasks (b, e-block)
        for (int task = bid; task < 256; task += NB_)
            awe_task(task >> 3, task & 7, bimgs, sm.al, tid);
        gridbar();

        // C: LSTM gates GEMM — 16 col x 8 K-chunk tasks
        if (bid < 128)
            cell_tile(bid & 15, bid >> 4, t, par, sm.tb, idx_s, W_ih, W_hh, embW, bx, tid);
        gridbar();

        // D: LSTM cell update
        lstm_stage(b_ih, b_hh, bxlen, t, par, gid);
        gridbar();

        // E: att2+gate partials from h(t) = hbuf[par^1]
        if (bid < 80) a2g_tile(bid, g_hbuf[par ^ 1], sm.tb, dec_att_W, f_beta_W, tid);
        gridbar();

        // F: reduce partials -> att2, gate
        a2g_reduce(dec_att_b, f_beta_b, gid);
        gridbar();
    }

    // final preds for t = T-1
    if (bid < 79)
        preds_tile(bid, T_ - 1, sm.tb, fc_W, fc_b, bxlen, out_pred, tid);
}

// ----------------------------- launch --------------------------------------
extern "C" void kernel_launch(void* const* d_in, const int* in_sizes, int n_in,
                              void* d_out, int out_size) {
    (void)in_sizes; (void)n_in; (void)out_size;
    const float* bimgs      = (const float*)d_in[0];
    const int*   bx         = (const int*)  d_in[1];
    const int*   bxlen      = (const int*)  d_in[2];
    const float* emb_W      = (const float*)d_in[3];
    const float* enc_att_W  = (const float*)d_in[4];
    const float* enc_att_b  = (const float*)d_in[5];
    const float* dec_att_W  = (const float*)d_in[6];
    const float* dec_att_b  = (const float*)d_in[7];
    const float* full_att_W = (const float*)d_in[8];
    const float* full_att_b = (const float*)d_in[9];
    const float* init_h_W   = (const float*)d_in[10];
    const float* init_h_b   = (const float*)d_in[11];
    const float* init_c_W   = (const float*)d_in[12];
    const float* init_c_b   = (const float*)d_in[13];
    const float* f_beta_W   = (const float*)d_in[14];
    const float* f_beta_b   = (const float*)d_in[15];
    const float* W_ih       = (const float*)d_in[16];
    const float* b_ih       = (const float*)d_in[17];
    const float* W_hh       = (const float*)d_in[18];
    const float* b_hh       = (const float*)d_in[19];
    const float* fc_W       = (const float*)d_in[20];
    const float* fc_b       = (const float*)d_in[21];

    float* out_pred  = (float*)d_out;
    float* out_alpha = out_pred + (size_t)B_ * T_ * V_;

    k_mean<<<256, 256>>>(bimgs);
    k_att1<<<dim3(8, 196), 128>>>(bimgs, enc_att_W, enc_att_b);
    k_init<<<16, 128>>>(init_h_W, init_c_W, init_h_b, init_c_b);

    k_loop<<<NB_, 256>>>(bimgs, bx, bxlen, emb_W,
                         dec_att_W, dec_att_b, full_att_W, full_att_b,
                         f_beta_W, f_beta_b, W_ih, b_ih, W_hh, b_hh,
                         fc_W, fc_b, out_pred, out_alpha);
}